// round 12
// baseline (speedup 1.0000x reference)
#include <cuda_runtime.h>
#include <cuda_fp16.h>
#include <cstdint>
#include <cstddef>

#define BB 4
#define SS 2048
#define DD 1024
#define ND3 (3 * DD)    // packed QKV width = 3072

// Scratch (__device__ globals; allocation-free rule)
__device__ __half g_X16[BB * SS * DD];
__device__ __half g_Wcat16[ND3 * DD];              // [Wq; Wk; Wv] rows
__device__ __half g_QKV16[(size_t)BB * SS * ND3];  // [B*S, 3072]: Q|K|(V unused)
__device__ __half g_VT16[BB * SS * DD];            // per batch [D, S]
__device__ __half g_P16[(size_t)BB * SS * SS];     // unnormalized exp scores
__device__ float  g_rs[BB * SS * 16];              // per-(row, bxTile) partial sums

// exp2 factor: (1/sqrt(1024)) * log2(e)
#define EXPC 0.0450842200277801f

__device__ __forceinline__ uint32_t smem_u32(const void* p) {
    uint32_t a;
    asm("{ .reg .u64 t; cvta.to.shared.u64 t, %1; cvt.u32.u64 %0, t; }" : "=r"(a) : "l"(p));
    return a;
}
__device__ __forceinline__ void cp16(uint32_t dst, const void* src) {
    asm volatile("cp.async.cg.shared.global [%0], [%1], 16;" :: "r"(dst), "l"(src) : "memory");
}
__device__ __forceinline__ void ldsm_x4(uint32_t& r0, uint32_t& r1, uint32_t& r2,
                                        uint32_t& r3, uint32_t addr) {
    asm volatile("ldmatrix.sync.aligned.m8n8.x4.shared.b16 {%0,%1,%2,%3}, [%4];"
                 : "=r"(r0), "=r"(r1), "=r"(r2), "=r"(r3) : "r"(addr));
}
__device__ __forceinline__ void mma_fp16(float c[4], uint32_t a0, uint32_t a1,
                                         uint32_t a2, uint32_t a3,
                                         uint32_t b0, uint32_t b1) {
    asm volatile(
        "mma.sync.aligned.m16n8k16.row.col.f32.f16.f16.f32 "
        "{%0,%1,%2,%3}, {%4,%5,%6,%7}, {%8,%9}, {%0,%1,%2,%3};\n"
        : "+f"(c[0]), "+f"(c[1]), "+f"(c[2]), "+f"(c[3])
        : "r"(a0), "r"(a1), "r"(a2), "r"(a3), "r"(b0), "r"(b1));
}

#define BK 64
#define OPB (128 * 128)               // bytes per operand region
#define STG_BYTES (2 * OPB)           // 32768 per stage
#define STAGES 3
#define SMEM_BYTES (STAGES * STG_BYTES + 512)
#define INV_OFF (STAGES * STG_BYTES)

// ===================== PROJECTION GEMM ==================
// 256 thr, 8 warps of 64x32, CTA 128x96 (NFRAG=3). V cols -> VT transposed.
// ks order staggered per warp column to decorrelate LDSM bursts.
template<int NFRAG, int LDA, int LDB, int LDC>
__global__ void __launch_bounds__(256, 2) mm_proj(
    const __half* __restrict__ Ab, const __half* __restrict__ Bb,
    __half* __restrict__ Cb, __half* __restrict__ VTOut, int K)
{
    constexpr int NTILE = NFRAG * 32;
    constexpr int WN    = NFRAG * 8;
    const int bx = blockIdx.x, by = blockIdx.y;

    extern __shared__ __align__(128) char smem[];
    const uint32_t sb = smem_u32(smem);

    const int tid  = threadIdx.x;
    const int wid  = tid >> 5, lane = tid & 31;
    const int wm   = wid & 1;
    const int wn   = wid >> 1;
    const int gid  = lane >> 2;
    const int tig  = lane & 3;
    const int kst  = (wn & 1) << 1;      // ks stagger: 0 or 2

    const __half* A = Ab + (size_t)by * 128 * LDA;
    const __half* B = Bb + (size_t)bx * NTILE * LDB;
    const int NC = K / BK;

    const uint32_t swz    = lane & 7;
    const uint32_t rowA   = wm * 64 + (lane & 15);
    const uint32_t chalfA = lane >> 4;
    const uint32_t rowB   = wn * WN + (lane & 7) + ((lane >> 4) << 3);
    const uint32_t chalfB = (lane >> 3) & 1;

    auto issue_chunk = [&](int c) {
        const int stg = c - (c / 3) * 3;
        const uint32_t ab = sb + stg * STG_BYTES;
        const uint32_t bb = ab + OPB;
        const int k0 = c * BK;
        #pragma unroll
        for (int i = 0; i < 4; i++) {
            int s = tid + i * 256;
            uint32_t r = s >> 3, f = s & 7;
            uint32_t d = r * 128 + ((f ^ (r & 7)) << 4);
            cp16(ab + d, A + (size_t)r * LDA + k0 + f * 8);
        }
        #pragma unroll
        for (int i = 0; i < NFRAG; i++) {
            int s = tid + i * 256;
            uint32_t r = s >> 3, f = s & 7;
            uint32_t d = r * 128 + ((f ^ (r & 7)) << 4);
            cp16(bb + d, B + (size_t)r * LDB + k0 + f * 8);
        }
        asm volatile("cp.async.commit_group;" ::: "memory");
    };

    float acc[4][NFRAG][4];
    #pragma unroll
    for (int i = 0; i < 4; i++)
        #pragma unroll
        for (int j = 0; j < NFRAG; j++)
            #pragma unroll
            for (int t = 0; t < 4; t++) acc[i][j][t] = 0.f;

    issue_chunk(0); issue_chunk(1);

    for (int c = 0; c < NC; c++) {
        asm volatile("cp.async.wait_group 1;" ::: "memory");
        __syncthreads();
        if (c + 2 < NC) issue_chunk(c + 2);
        else asm volatile("cp.async.commit_group;" ::: "memory");

        const int stg = c - (c / 3) * 3;
        const uint32_t ab = sb + stg * STG_BYTES;
        const uint32_t bb = ab + OPB;

        #pragma unroll
        for (int ksi = 0; ksi < 4; ksi++) {
            const int ks = ksi ^ kst;            // staggered k16 order
            uint32_t afr[4][4], bfr[2][4];
            #pragma unroll
            for (int mt = 0; mt < 4; mt++)
                ldsm_x4(afr[mt][0], afr[mt][1], afr[mt][2], afr[mt][3],
                        ab + (rowA + mt * 16) * 128
                           + ((((ks << 1) | chalfA) ^ swz) << 4));
            #pragma unroll
            for (int nt2 = 0; nt2 < 2; nt2++)
                ldsm_x4(bfr[nt2][0], bfr[nt2][1], bfr[nt2][2], bfr[nt2][3],
                        bb + (rowB + nt2 * 16) * 128
                           + ((((ks << 1) | chalfB) ^ swz) << 4));
            #pragma unroll
            for (int mt = 0; mt < 4; mt++)
                #pragma unroll
                for (int nt = 0; nt < NFRAG; nt++)
                    mma_fp16(acc[mt][nt], afr[mt][0], afr[mt][1], afr[mt][2],
                             afr[mt][3], bfr[nt >> 1][(nt & 1) * 2],
                             bfr[nt >> 1][(nt & 1) * 2 + 1]);
        }
    }

    const bool vtile = (bx * NTILE + NTILE - 1) >= 2 * DD;
    __half* C = Cb + (size_t)by * 128 * LDC + (size_t)bx * NTILE;
    #pragma unroll
    for (int mt = 0; mt < 4; mt++) {
        int row0 = wm * 64 + mt * 16 + gid;
        #pragma unroll
        for (int nt = 0; nt < NFRAG; nt++) {
            int col0 = wn * WN + nt * 8 + tig * 2;
            if (!vtile || bx * NTILE + col0 < 2 * DD) {
                *(__half2*)(C + (size_t)row0       * LDC + col0) =
                    __floats2half2_rn(acc[mt][nt][0], acc[mt][nt][1]);
                *(__half2*)(C + (size_t)(row0 + 8) * LDC + col0) =
                    __floats2half2_rn(acc[mt][nt][2], acc[mt][nt][3]);
            }
        }
    }
    if (vtile) {
        __syncthreads();
        __half* smt = (__half*)smem;     // [NTILE][128]
        #pragma unroll
        for (int mt = 0; mt < 4; mt++) {
            int row0 = wm * 64 + mt * 16 + gid;
            #pragma unroll
            for (int nt = 0; nt < NFRAG; nt++) {
                int col0 = wn * WN + nt * 8 + tig * 2;
                smt[(col0)     * 128 + row0]     = __float2half_rn(acc[mt][nt][0]);
                smt[(col0 + 1) * 128 + row0]     = __float2half_rn(acc[mt][nt][1]);
                smt[(col0)     * 128 + row0 + 8] = __float2half_rn(acc[mt][nt][2]);
                smt[(col0 + 1) * 128 + row0 + 8] = __float2half_rn(acc[mt][nt][3]);
            }
        }
        __syncthreads();
        int b  = by >> 4;
        int s0 = (by & 15) * 128;
        __half* VTb = VTOut + (size_t)b * SS * DD;
        for (int i = tid; i < NTILE * 16; i += 256) {
            int c2 = i >> 4, ch = i & 15;
            int gcol = bx * NTILE + c2;
            if (gcol >= 2 * DD) {
                uint4 v = ((const uint4*)(smt + c2 * 128))[ch];
                *(uint4*)(VTb + (size_t)(gcol - 2 * DD) * SS + s0 + ch * 8) = v;
            }
        }
    }
}

// ===================== SCORES / PV GEMM: 64x64 warp tiles ===================
// 128 thr, 4 warps (2x2 of 64x64), CTA 128x128, 2 CTAs/SM.
// ks order staggered per warp column.
// MODE 1: exp2+mask scores, triangular grid, row-partial sums to Rs
// MODE 2: O = inv[row] * (P~ . V), heavy-first 1D grid
template<int MODE, int LDA, int LDB, int LDC,
         long long SA, long long SB, long long SC>
__global__ void __launch_bounds__(128, 2) mm_w64(
    const __half* __restrict__ Ab, const __half* __restrict__ Bb, void* __restrict__ Cb,
    const float* __restrict__ Rs, float* __restrict__ RsOut, int K)
{
    int bx, by, bz;
    if (MODE == 1) {            // triangular-packed: blockIdx.x -> (bx <= by)
        int t = blockIdx.x;
        by = (int)((sqrtf(8.f * (float)t + 1.f) - 1.f) * 0.5f);
        while ((by + 1) * (by + 2) / 2 <= t) by++;
        while (by * (by + 1) / 2 > t)       by--;
        bx = t - by * (by + 1) / 2;
        bz = blockIdx.z;
    } else {                    // heavy-first 1D
        int i = blockIdx.x;
        by = (SS / 128 - 1) - (i >> 5);
        int inner = i & 31;
        bz = inner >> 3;
        bx = inner & 7;
    }

    extern __shared__ __align__(128) char smem[];
    const uint32_t sb = smem_u32(smem);

    const int tid  = threadIdx.x;
    const int wid  = tid >> 5, lane = tid & 31;
    const int wm   = wid & 1;            // warp row -> 64 rows
    const int wn   = wid >> 1;           // warp col -> 64 cols
    const int gid  = lane >> 2;
    const int tig  = lane & 3;
    const int kst  = wn << 1;            // ks stagger: 0 or 2

    const __half* A = Ab + bz * SA + (size_t)by * 128 * LDA;
    const __half* B = Bb + bz * SB + (size_t)bx * 128 * LDB;

    const int kend = (MODE == 2) ? min(K, (by + 1) * 128) : K;
    const int NC   = kend / BK;

    const uint32_t swz    = lane & 7;
    const uint32_t rowA   = wm * 64 + (lane & 15);
    const uint32_t chalfA = lane >> 4;
    const uint32_t rowB   = wn * 64 + (lane & 7) + ((lane >> 4) << 3);
    const uint32_t chalfB = (lane >> 3) & 1;

    auto issue_chunk = [&](int c) {
        const int stg = c - (c / 3) * 3;
        const uint32_t ab = sb + stg * STG_BYTES;
        const uint32_t bb = ab + OPB;
        const int k0 = c * BK;
        #pragma unroll
        for (int i = 0; i < 8; i++) {
            int s = tid + i * 128;
            uint32_t r = s >> 3, f = s & 7;
            uint32_t d = r * 128 + ((f ^ (r & 7)) << 4);
            cp16(ab + d, A + (size_t)r * LDA + k0 + f * 8);
        }
        #pragma unroll
        for (int i = 0; i < 8; i++) {
            int s = tid + i * 128;
            uint32_t r = s >> 3, f = s & 7;
            uint32_t d = r * 128 + ((f ^ (r & 7)) << 4);
            cp16(bb + d, B + (size_t)r * LDB + k0 + f * 8);
        }
        asm volatile("cp.async.commit_group;" ::: "memory");
    };

    float acc[4][8][4];
    #pragma unroll
    for (int i = 0; i < 4; i++)
        #pragma unroll
        for (int j = 0; j < 8; j++)
            #pragma unroll
            for (int t = 0; t < 4; t++) acc[i][j][t] = 0.f;

    issue_chunk(0); issue_chunk(1);

    // MODE 2 prologue: 1/rowsum for this CTA's 128 rows (one per thread)
    if (MODE == 2) {
        const float* rs = Rs + ((size_t)bz * SS + by * 128 + tid) * 16;
        float s = 0.f;
        for (int j = 0; j <= by; j++) s += rs[j];
        ((float*)(smem + INV_OFF))[tid] = 1.0f / s;
    }

    // diagonal score tiles: warp (wm=0, wn=1) output fully masked -> skip math
    const bool dead = (MODE == 1) && (bx == by) && (wm == 0) && (wn == 1);

    for (int c = 0; c < NC; c++) {
        asm volatile("cp.async.wait_group 1;" ::: "memory");
        __syncthreads();
        if (c + 2 < NC) issue_chunk(c + 2);
        else asm volatile("cp.async.commit_group;" ::: "memory");

        const int stg = c - (c / 3) * 3;
        const uint32_t ab = sb + stg * STG_BYTES;
        const uint32_t bb = ab + OPB;

        if (!dead) {
            #pragma unroll
            for (int ksi = 0; ksi < 4; ksi++) {
                const int ks = ksi ^ kst;        // staggered k16 order
                uint32_t afr[4][4], bfr[4][4];
                #pragma unroll
                for (int mt = 0; mt < 4; mt++)
                    ldsm_x4(afr[mt][0], afr[mt][1], afr[mt][2], afr[mt][3],
                            ab + (rowA + mt * 16) * 128
                               + ((((ks << 1) | chalfA) ^ swz) << 4));
                #pragma unroll
                for (int nt2 = 0; nt2 < 4; nt2++)
                    ldsm_x4(bfr[nt2][0], bfr[nt2][1], bfr[nt2][2], bfr[nt2][3],
                            bb + (rowB + nt2 * 16) * 128
                               + ((((ks << 1) | chalfB) ^ swz) << 4));
                #pragma unroll
                for (int mt = 0; mt < 4; mt++)
                    #pragma unroll
                    for (int nt = 0; nt < 8; nt++)
                        mma_fp16(acc[mt][nt], afr[mt][0], afr[mt][1], afr[mt][2],
                                 afr[mt][3], bfr[nt >> 1][(nt & 1) * 2],
                                 bfr[nt >> 1][(nt & 1) * 2 + 1]);
            }
        }
    }

    if (MODE == 1) {
        __half* C = (__half*)Cb + bz * SC + (size_t)by * 128 * LDC
                  + (size_t)bx * 128;
        float srow[4][2];
        #pragma unroll
        for (int mt = 0; mt < 4; mt++) { srow[mt][0] = 0.f; srow[mt][1] = 0.f; }

        #pragma unroll
        for (int mt = 0; mt < 4; mt++) {
            int row0 = wm * 64 + mt * 16 + gid;
            int grow0 = by * 128 + row0;        // q
            #pragma unroll
            for (int nt = 0; nt < 8; nt++) {
                int col0 = wn * 64 + nt * 8 + tig * 2;
                int gcol0 = bx * 128 + col0;    // k
                float v0 = (gcol0     <= grow0)     ? exp2f(acc[mt][nt][0] * EXPC) : 0.f;
                float v1 = (gcol0 + 1 <= grow0)     ? exp2f(acc[mt][nt][1] * EXPC) : 0.f;
                float v2 = (gcol0     <= grow0 + 8) ? exp2f(acc[mt][nt][2] * EXPC) : 0.f;
                float v3 = (gcol0 + 1 <= grow0 + 8) ? exp2f(acc[mt][nt][3] * EXPC) : 0.f;
                srow[mt][0] += v0 + v1;
                srow[mt][1] += v2 + v3;
                *(__half2*)(C + (size_t)row0       * LDC + col0) = __floats2half2_rn(v0, v1);
                *(__half2*)(C + (size_t)(row0 + 8) * LDC + col0) = __floats2half2_rn(v2, v3);
            }
        }
        #pragma unroll
        for (int mt = 0; mt < 4; mt++) {
            #pragma unroll
            for (int h = 0; h < 2; h++) {
                float s = srow[mt][h];
                s += __shfl_xor_sync(0xFFFFFFFFu, s, 1);
                s += __shfl_xor_sync(0xFFFFFFFFu, s, 2);
                srow[mt][h] = s;
            }
        }
        __syncthreads();
        float* part = (float*)smem;             // [128][2]
        if (tig == 0) {
            #pragma unroll
            for (int mt = 0; mt < 4; mt++) {
                int rl = wm * 64 + mt * 16 + gid;
                part[rl * 2 + wn]       = srow[mt][0];
                part[(rl + 8) * 2 + wn] = srow[mt][1];
            }
        }
        __syncthreads();
        {
            float s = part[tid * 2] + part[tid * 2 + 1];
            RsOut[((size_t)bz * SS + by * 128 + tid) * 16 + bx] = s;
        }
    } else {
        float* C = (float*)Cb + bz * SC + (size_t)by * 128 * LDC
                 + (size_t)bx * 128;
        const float* invs = (const float*)(smem + INV_OFF);
        #pragma unroll
        for (int mt = 0; mt < 4; mt++) {
            int row0 = wm * 64 + mt * 16 + gid;
            float ia = invs[row0];
            float ib = invs[row0 + 8];
            #pragma unroll
            for (int nt = 0; nt < 8; nt++) {
                int col0 = wn * 64 + nt * 8 + tig * 2;
                *(float2*)(C + (size_t)row0       * LDC + col0) =
                    make_float2(acc[mt][nt][0] * ia, acc[mt][nt][1] * ia);
                *(float2*)(C + (size_t)(row0 + 8) * LDC + col0) =
                    make_float2(acc[mt][nt][2] * ib, acc[mt][nt][3] * ib);
            }
        }
    }
}

// ===================== fused fp32 -> fp16 convert (x | Wq | Wk | Wv) =========
__global__ void __launch_bounds__(256) cvt_all_kernel(
    const float* __restrict__ x,  const float* __restrict__ Wq,
    const float* __restrict__ Wk, const float* __restrict__ Wv,
    __half* __restrict__ X16, __half* __restrict__ Wcat)
{
    int blk = blockIdx.x;
    const float* src;
    __half* dst;
    size_t idx;
    if (blk < 8192) {
        src = x; dst = X16;
        idx = (size_t)blk * 256 + threadIdx.x;
    } else {
        int k = blk - 8192;          // 0..3071
        int w = k >> 10;             // which weight
        src = (w == 0) ? Wq : (w == 1) ? Wk : Wv;
        dst = Wcat + (size_t)w * DD * DD;
        idx = (size_t)(k & 1023) * 256 + threadIdx.x;
    }
    float4 v = ((const float4*)src)[idx];
    ((__half2*)dst)[idx * 2]     = __floats2half2_rn(v.x, v.y);
    ((__half2*)dst)[idx * 2 + 1] = __floats2half2_rn(v.z, v.w);
}

// ===========================================================================
extern "C" void kernel_launch(void* const* d_in, const int* in_sizes, int n_in,
                              void* d_out, int out_size)
{
    const float* x  = (const float*)d_in[0];
    const float* Wq = (const float*)d_in[1];
    const float* Wk = (const float*)d_in[2];
    const float* Wv = (const float*)d_in[3];
    float* out = (float*)d_out;

    __half *X16, *Wcat, *QKV, *VT16, *P16;
    float *rsp;
    cudaGetSymbolAddress((void**)&X16,  g_X16);
    cudaGetSymbolAddress((void**)&Wcat, g_Wcat16);
    cudaGetSymbolAddress((void**)&QKV,  g_QKV16);
    cudaGetSymbolAddress((void**)&VT16, g_VT16);
    cudaGetSymbolAddress((void**)&P16,  g_P16);
    cudaGetSymbolAddress((void**)&rsp,  g_rs);

    constexpr long long sQKV3 = (long long)SS * ND3;
    constexpr long long sV    = (long long)SS * DD;
    constexpr long long sP    = (long long)SS * SS;

    auto kProj  = mm_proj<3, DD, DD, ND3>;
    auto kScore = mm_w64<1, ND3, ND3, SS, sQKV3, sQKV3, sP>;
    auto kOut   = mm_w64<2, SS,  SS,  DD, sP,    sV,    sV>;

    cudaFuncSetAttribute(kProj,  cudaFuncAttributeMaxDynamicSharedMemorySize, SMEM_BYTES);
    cudaFuncSetAttribute(kScore, cudaFuncAttributeMaxDynamicSharedMemorySize, SMEM_BYTES);
    cudaFuncSetAttribute(kOut,   cudaFuncAttributeMaxDynamicSharedMemorySize, SMEM_BYTES);

    // 0) fused fp32 -> fp16 conversion (x + all weights, one launch)
    cvt_all_kernel<<<8192 + 3 * 1024, 256>>>(x, Wq, Wk, Wv, X16, Wcat);

    // 1) Fused QKV projection; V columns written transposed to VT16
    dim3 gProj(ND3 / 96, (BB * SS) / 128, 1);
    kProj<<<gProj, 256, SMEM_BYTES>>>(X16, Wcat, QKV, VT16, DD);

    // 2) Scores + exp + mask + row-partial sums; triangular-packed grid
    const int TTILES = (SS / 128) * (SS / 128 + 1) / 2;   // 136
    dim3 gScore(TTILES, 1, BB);
    kScore<<<gScore, 128, SMEM_BYTES>>>(QKV, QKV + DD, P16, nullptr, rsp, DD);

    // 3) O = diag(1/rowsum) * (P~ @ V); heavy-first 1D grid
    dim3 gOut((DD / 128) * (SS / 128) * BB, 1, 1);
    kOut<<<gOut, 128, SMEM_BYTES>>>(P16, VT16, out, rsp, nullptr, SS);
}

// round 15
// speedup vs baseline: 1.0160x; 1.0160x over previous
#include <cuda_runtime.h>
#include <cuda_fp16.h>
#include <cstdint>
#include <cstddef>

#define BB 4
#define SS 2048
#define DD 1024
#define ND3 (3 * DD)    // packed QKV width = 3072

// Scratch (__device__ globals; allocation-free rule)
__device__ __half g_X16[BB * SS * DD];
__device__ __half g_Wcat16[ND3 * DD];              // [Wq; Wk; Wv] rows
__device__ __half g_QKV16[(size_t)BB * SS * ND3];  // [B*S, 3072]: Q|K|(V unused)
__device__ __half g_VT16[BB * SS * DD];            // per batch [D, S]
__device__ __half g_P16[(size_t)BB * SS * SS];     // unnormalized exp scores
__device__ float  g_rs[BB * SS * 16];              // per-(row, bxTile) partial sums

// exp2 factor: (1/sqrt(1024)) * log2(e)
#define EXPC 0.0450842200277801f

__device__ __forceinline__ uint32_t smem_u32(const void* p) {
    uint32_t a;
    asm("{ .reg .u64 t; cvta.to.shared.u64 t, %1; cvt.u32.u64 %0, t; }" : "=r"(a) : "l"(p));
    return a;
}
__device__ __forceinline__ void cp16(uint32_t dst, const void* src) {
    asm volatile("cp.async.cg.shared.global [%0], [%1], 16;" :: "r"(dst), "l"(src) : "memory");
}
__device__ __forceinline__ void ldsm_x4(uint32_t& r0, uint32_t& r1, uint32_t& r2,
                                        uint32_t& r3, uint32_t addr) {
    asm volatile("ldmatrix.sync.aligned.m8n8.x4.shared.b16 {%0,%1,%2,%3}, [%4];"
                 : "=r"(r0), "=r"(r1), "=r"(r2), "=r"(r3) : "r"(addr));
}
__device__ __forceinline__ void mma_fp16(float c[4], uint32_t a0, uint32_t a1,
                                         uint32_t a2, uint32_t a3,
                                         uint32_t b0, uint32_t b1) {
    asm volatile(
        "mma.sync.aligned.m16n8k16.row.col.f32.f16.f16.f32 "
        "{%0,%1,%2,%3}, {%4,%5,%6,%7}, {%8,%9}, {%0,%1,%2,%3};\n"
        : "+f"(c[0]), "+f"(c[1]), "+f"(c[2]), "+f"(c[3])
        : "r"(a0), "r"(a1), "r"(a2), "r"(a3), "r"(b0), "r"(b1));
}

#define BK 64
#define OPB (128 * 128)               // bytes per operand region
#define STG_BYTES (2 * OPB)           // 32768 per stage
#define STAGES 3
#define SMEM_BYTES (STAGES * STG_BYTES + 512)
#define INV_OFF (STAGES * STG_BYTES)

// ===================== PROJECTION GEMM ==================
// 256 thr, 8 warps of 64x32, CTA 128x96 (NFRAG=3). V cols -> VT transposed.
template<int NFRAG, int LDA, int LDB, int LDC>
__global__ void __launch_bounds__(256, 2) mm_proj(
    const __half* __restrict__ Ab, const __half* __restrict__ Bb,
    __half* __restrict__ Cb, __half* __restrict__ VTOut, int K)
{
    constexpr int NTILE = NFRAG * 32;
    constexpr int WN    = NFRAG * 8;
    const int bx = blockIdx.x, by = blockIdx.y;

    extern __shared__ __align__(128) char smem[];
    const uint32_t sb = smem_u32(smem);

    const int tid  = threadIdx.x;
    const int wid  = tid >> 5, lane = tid & 31;
    const int wm   = wid & 1;
    const int wn   = wid >> 1;
    const int gid  = lane >> 2;
    const int tig  = lane & 3;

    const __half* A = Ab + (size_t)by * 128 * LDA;
    const __half* B = Bb + (size_t)bx * NTILE * LDB;
    const int NC = K / BK;

    const uint32_t swz    = lane & 7;
    const uint32_t rowA   = wm * 64 + (lane & 15);
    const uint32_t chalfA = lane >> 4;
    const uint32_t rowB   = wn * WN + (lane & 7) + ((lane >> 4) << 3);
    const uint32_t chalfB = (lane >> 3) & 1;

    auto issue_chunk = [&](int c) {
        const int stg = c - (c / 3) * 3;
        const uint32_t ab = sb + stg * STG_BYTES;
        const uint32_t bb = ab + OPB;
        const int k0 = c * BK;
        #pragma unroll
        for (int i = 0; i < 4; i++) {
            int s = tid + i * 256;
            uint32_t r = s >> 3, f = s & 7;
            uint32_t d = r * 128 + ((f ^ (r & 7)) << 4);
            cp16(ab + d, A + (size_t)r * LDA + k0 + f * 8);
        }
        #pragma unroll
        for (int i = 0; i < NFRAG; i++) {
            int s = tid + i * 256;
            uint32_t r = s >> 3, f = s & 7;
            uint32_t d = r * 128 + ((f ^ (r & 7)) << 4);
            cp16(bb + d, B + (size_t)r * LDB + k0 + f * 8);
        }
        asm volatile("cp.async.commit_group;" ::: "memory");
    };

    float acc[4][NFRAG][4];
    #pragma unroll
    for (int i = 0; i < 4; i++)
        #pragma unroll
        for (int j = 0; j < NFRAG; j++)
            #pragma unroll
            for (int t = 0; t < 4; t++) acc[i][j][t] = 0.f;

    issue_chunk(0); issue_chunk(1);

    for (int c = 0; c < NC; c++) {
        asm volatile("cp.async.wait_group 1;" ::: "memory");
        __syncthreads();
        if (c + 2 < NC) issue_chunk(c + 2);
        else asm volatile("cp.async.commit_group;" ::: "memory");

        const int stg = c - (c / 3) * 3;
        const uint32_t ab = sb + stg * STG_BYTES;
        const uint32_t bb = ab + OPB;

        #pragma unroll
        for (int ks = 0; ks < 4; ks++) {
            uint32_t afr[4][4], bfr[2][4];
            #pragma unroll
            for (int mt = 0; mt < 4; mt++)
                ldsm_x4(afr[mt][0], afr[mt][1], afr[mt][2], afr[mt][3],
                        ab + (rowA + mt * 16) * 128
                           + ((((ks << 1) | chalfA) ^ swz) << 4));
            #pragma unroll
            for (int nt2 = 0; nt2 < 2; nt2++)
                ldsm_x4(bfr[nt2][0], bfr[nt2][1], bfr[nt2][2], bfr[nt2][3],
                        bb + (rowB + nt2 * 16) * 128
                           + ((((ks << 1) | chalfB) ^ swz) << 4));
            #pragma unroll
            for (int mt = 0; mt < 4; mt++)
                #pragma unroll
                for (int nt = 0; nt < NFRAG; nt++)
                    mma_fp16(acc[mt][nt], afr[mt][0], afr[mt][1], afr[mt][2],
                             afr[mt][3], bfr[nt >> 1][(nt & 1) * 2],
                             bfr[nt >> 1][(nt & 1) * 2 + 1]);
        }
    }

    const bool vtile = (bx * NTILE + NTILE - 1) >= 2 * DD;
    __half* C = Cb + (size_t)by * 128 * LDC + (size_t)bx * NTILE;
    #pragma unroll
    for (int mt = 0; mt < 4; mt++) {
        int row0 = wm * 64 + mt * 16 + gid;
        #pragma unroll
        for (int nt = 0; nt < NFRAG; nt++) {
            int col0 = wn * WN + nt * 8 + tig * 2;
            if (!vtile || bx * NTILE + col0 < 2 * DD) {
                *(__half2*)(C + (size_t)row0       * LDC + col0) =
                    __floats2half2_rn(acc[mt][nt][0], acc[mt][nt][1]);
                *(__half2*)(C + (size_t)(row0 + 8) * LDC + col0) =
                    __floats2half2_rn(acc[mt][nt][2], acc[mt][nt][3]);
            }
        }
    }
    if (vtile) {
        __syncthreads();
        __half* smt = (__half*)smem;     // [NTILE][128]
        #pragma unroll
        for (int mt = 0; mt < 4; mt++) {
            int row0 = wm * 64 + mt * 16 + gid;
            #pragma unroll
            for (int nt = 0; nt < NFRAG; nt++) {
                int col0 = wn * WN + nt * 8 + tig * 2;
                smt[(col0)     * 128 + row0]     = __float2half_rn(acc[mt][nt][0]);
                smt[(col0 + 1) * 128 + row0]     = __float2half_rn(acc[mt][nt][1]);
                smt[(col0)     * 128 + row0 + 8] = __float2half_rn(acc[mt][nt][2]);
                smt[(col0 + 1) * 128 + row0 + 8] = __float2half_rn(acc[mt][nt][3]);
            }
        }
        __syncthreads();
        int b  = by >> 4;
        int s0 = (by & 15) * 128;
        __half* VTb = VTOut + (size_t)b * SS * DD;
        for (int i = tid; i < NTILE * 16; i += 256) {
            int c2 = i >> 4, ch = i & 15;
            int gcol = bx * NTILE + c2;
            if (gcol >= 2 * DD) {
                uint4 v = ((const uint4*)(smt + c2 * 128))[ch];
                *(uint4*)(VTb + (size_t)(gcol - 2 * DD) * SS + s0 + ch * 8) = v;
            }
        }
    }
}

// ===================== SCORES / PV GEMM: 64x64 warp tiles ===================
// 128 thr, 4 warps (2x2 of 64x64), CTA 128x128, 2 CTAs/SM.
// MODE 1: exp2+mask scores, triangular grid, row-partial sums to Rs
// MODE 2: O = inv[row] * (P~ . V), heavy-first 1D grid
template<int MODE, int LDA, int LDB, int LDC,
         long long SA, long long SB, long long SC>
__global__ void __launch_bounds__(128, 2) mm_w64(
    const __half* __restrict__ Ab, const __half* __restrict__ Bb, void* __restrict__ Cb,
    const float* __restrict__ Rs, float* __restrict__ RsOut, int K)
{
    int bx, by, bz;
    if (MODE == 1) {            // triangular-packed: blockIdx.x -> (bx <= by)
        int t = blockIdx.x;
        by = (int)((sqrtf(8.f * (float)t + 1.f) - 1.f) * 0.5f);
        while ((by + 1) * (by + 2) / 2 <= t) by++;
        while (by * (by + 1) / 2 > t)       by--;
        bx = t - by * (by + 1) / 2;
        bz = blockIdx.z;
    } else {                    // heavy-first 1D
        int i = blockIdx.x;
        by = (SS / 128 - 1) - (i >> 5);
        int inner = i & 31;
        bz = inner >> 3;
        bx = inner & 7;
    }

    extern __shared__ __align__(128) char smem[];
    const uint32_t sb = smem_u32(smem);

    const int tid  = threadIdx.x;
    const int wid  = tid >> 5, lane = tid & 31;
    const int wm   = wid & 1;            // warp row -> 64 rows
    const int wn   = wid >> 1;           // warp col -> 64 cols
    const int gid  = lane >> 2;
    const int tig  = lane & 3;

    const __half* A = Ab + bz * SA + (size_t)by * 128 * LDA;
    const __half* B = Bb + bz * SB + (size_t)bx * 128 * LDB;

    const int kend = (MODE == 2) ? min(K, (by + 1) * 128) : K;
    const int NC   = kend / BK;

    const uint32_t swz    = lane & 7;
    const uint32_t rowA   = wm * 64 + (lane & 15);
    const uint32_t chalfA = lane >> 4;
    const uint32_t rowB   = wn * 64 + (lane & 7) + ((lane >> 4) << 3);
    const uint32_t chalfB = (lane >> 3) & 1;

    auto issue_chunk = [&](int c) {
        const int stg = c - (c / 3) * 3;
        const uint32_t ab = sb + stg * STG_BYTES;
        const uint32_t bb = ab + OPB;
        const int k0 = c * BK;
        #pragma unroll
        for (int i = 0; i < 8; i++) {
            int s = tid + i * 128;
            uint32_t r = s >> 3, f = s & 7;
            uint32_t d = r * 128 + ((f ^ (r & 7)) << 4);
            cp16(ab + d, A + (size_t)r * LDA + k0 + f * 8);
        }
        #pragma unroll
        for (int i = 0; i < 8; i++) {
            int s = tid + i * 128;
            uint32_t r = s >> 3, f = s & 7;
            uint32_t d = r * 128 + ((f ^ (r & 7)) << 4);
            cp16(bb + d, B + (size_t)r * LDB + k0 + f * 8);
        }
        asm volatile("cp.async.commit_group;" ::: "memory");
    };

    float acc[4][8][4];
    #pragma unroll
    for (int i = 0; i < 4; i++)
        #pragma unroll
        for (int j = 0; j < 8; j++)
            #pragma unroll
            for (int t = 0; t < 4; t++) acc[i][j][t] = 0.f;

    issue_chunk(0); issue_chunk(1);

    // MODE 2 prologue: 1/rowsum for this CTA's 128 rows (one per thread)
    if (MODE == 2) {
        const float* rs = Rs + ((size_t)bz * SS + by * 128 + tid) * 16;
        float s = 0.f;
        for (int j = 0; j <= by; j++) s += rs[j];
        ((float*)(smem + INV_OFF))[tid] = 1.0f / s;
    }

    // diagonal score tiles: warp (wm=0, wn=1) output fully masked -> skip math
    const bool dead = (MODE == 1) && (bx == by) && (wm == 0) && (wn == 1);

    for (int c = 0; c < NC; c++) {
        asm volatile("cp.async.wait_group 1;" ::: "memory");
        __syncthreads();
        if (c + 2 < NC) issue_chunk(c + 2);
        else asm volatile("cp.async.commit_group;" ::: "memory");

        const int stg = c - (c / 3) * 3;
        const uint32_t ab = sb + stg * STG_BYTES;
        const uint32_t bb = ab + OPB;

        if (!dead) {
            #pragma unroll
            for (int ks = 0; ks < 4; ks++) {
                uint32_t afr[4][4], bfr[4][4];
                #pragma unroll
                for (int mt = 0; mt < 4; mt++)
                    ldsm_x4(afr[mt][0], afr[mt][1], afr[mt][2], afr[mt][3],
                            ab + (rowA + mt * 16) * 128
                               + ((((ks << 1) | chalfA) ^ swz) << 4));
                #pragma unroll
                for (int nt2 = 0; nt2 < 4; nt2++)
                    ldsm_x4(bfr[nt2][0], bfr[nt2][1], bfr[nt2][2], bfr[nt2][3],
                            bb + (rowB + nt2 * 16) * 128
                               + ((((ks << 1) | chalfB) ^ swz) << 4));
                #pragma unroll
                for (int mt = 0; mt < 4; mt++)
                    #pragma unroll
                    for (int nt = 0; nt < 8; nt++)
                        mma_fp16(acc[mt][nt], afr[mt][0], afr[mt][1], afr[mt][2],
                                 afr[mt][3], bfr[nt >> 1][(nt & 1) * 2],
                                 bfr[nt >> 1][(nt & 1) * 2 + 1]);
            }
        }
    }

    if (MODE == 1) {
        __half* C = (__half*)Cb + bz * SC + (size_t)by * 128 * LDC
                  + (size_t)bx * 128;
        float srow[4][2];
        #pragma unroll
        for (int mt = 0; mt < 4; mt++) { srow[mt][0] = 0.f; srow[mt][1] = 0.f; }

        #pragma unroll
        for (int mt = 0; mt < 4; mt++) {
            int row0 = wm * 64 + mt * 16 + gid;
            int grow0 = by * 128 + row0;        // q
            #pragma unroll
            for (int nt = 0; nt < 8; nt++) {
                int col0 = wn * 64 + nt * 8 + tig * 2;
                int gcol0 = bx * 128 + col0;    // k
                float v0 = (gcol0     <= grow0)     ? exp2f(acc[mt][nt][0] * EXPC) : 0.f;
                float v1 = (gcol0 + 1 <= grow0)     ? exp2f(acc[mt][nt][1] * EXPC) : 0.f;
                float v2 = (gcol0     <= grow0 + 8) ? exp2f(acc[mt][nt][2] * EXPC) : 0.f;
                float v3 = (gcol0 + 1 <= grow0 + 8) ? exp2f(acc[mt][nt][3] * EXPC) : 0.f;
                srow[mt][0] += v0 + v1;
                srow[mt][1] += v2 + v3;
                *(__half2*)(C + (size_t)row0       * LDC + col0) = __floats2half2_rn(v0, v1);
                *(__half2*)(C + (size_t)(row0 + 8) * LDC + col0) = __floats2half2_rn(v2, v3);
            }
        }
        #pragma unroll
        for (int mt = 0; mt < 4; mt++) {
            #pragma unroll
            for (int h = 0; h < 2; h++) {
                float s = srow[mt][h];
                s += __shfl_xor_sync(0xFFFFFFFFu, s, 1);
                s += __shfl_xor_sync(0xFFFFFFFFu, s, 2);
                srow[mt][h] = s;
            }
        }
        __syncthreads();
        float* part = (float*)smem;             // [128][2]
        if (tig == 0) {
            #pragma unroll
            for (int mt = 0; mt < 4; mt++) {
                int rl = wm * 64 + mt * 16 + gid;
                part[rl * 2 + wn]       = srow[mt][0];
                part[(rl + 8) * 2 + wn] = srow[mt][1];
            }
        }
        __syncthreads();
        {
            float s = part[tid * 2] + part[tid * 2 + 1];
            RsOut[((size_t)bz * SS + by * 128 + tid) * 16 + bx] = s;
        }
    } else {
        float* C = (float*)Cb + bz * SC + (size_t)by * 128 * LDC
                 + (size_t)bx * 128;
        const float* invs = (const float*)(smem + INV_OFF);
        #pragma unroll
        for (int mt = 0; mt < 4; mt++) {
            int row0 = wm * 64 + mt * 16 + gid;
            float ia = invs[row0];
            float ib = invs[row0 + 8];
            #pragma unroll
            for (int nt = 0; nt < 8; nt++) {
                int col0 = wn * 64 + nt * 8 + tig * 2;
                *(float2*)(C + (size_t)row0       * LDC + col0) =
                    make_float2(acc[mt][nt][0] * ia, acc[mt][nt][1] * ia);
                *(float2*)(C + (size_t)(row0 + 8) * LDC + col0) =
                    make_float2(acc[mt][nt][2] * ib, acc[mt][nt][3] * ib);
            }
        }
    }
}

// ===================== fused fp32 -> fp16 convert (8 floats/thread) ==========
// layout: blocks [0, 4096) -> x (8M floats), [4096, 5632) -> Wq|Wk|Wv (3M)
__global__ void __launch_bounds__(256) cvt_all_kernel(
    const float* __restrict__ x,  const float* __restrict__ Wq,
    const float* __restrict__ Wk, const float* __restrict__ Wv,
    __half* __restrict__ X16, __half* __restrict__ Wcat)
{
    int blk = blockIdx.x;
    const float* src;
    __half* dst;
    size_t base;                 // in 8-float units
    if (blk < 4096) {
        src = x; dst = X16;
        base = (size_t)blk * 256 + threadIdx.x;
    } else {
        int k = blk - 4096;          // 0..1535
        int w = k / 512;             // which weight
        src = (w == 0) ? Wq : (w == 1) ? Wk : Wv;
        dst = Wcat + (size_t)w * DD * DD;
        base = (size_t)(k - w * 512) * 256 + threadIdx.x;
    }
    float4 v0 = ((const float4*)src)[base * 2];
    float4 v1 = ((const float4*)src)[base * 2 + 1];
    __half2 hh[4];
    hh[0] = __floats2half2_rn(v0.x, v0.y);
    hh[1] = __floats2half2_rn(v0.z, v0.w);
    hh[2] = __floats2half2_rn(v1.x, v1.y);
    hh[3] = __floats2half2_rn(v1.z, v1.w);
    ((uint4*)dst)[base] = *reinterpret_cast<const uint4*>(hh);
}

// ===========================================================================
extern "C" void kernel_launch(void* const* d_in, const int* in_sizes, int n_in,
                              void* d_out, int out_size)
{
    const float* x  = (const float*)d_in[0];
    const float* Wq = (const float*)d_in[1];
    const float* Wk = (const float*)d_in[2];
    const float* Wv = (const float*)d_in[3];
    float* out = (float*)d_out;

    __half *X16, *Wcat, *QKV, *VT16, *P16;
    float *rsp;
    cudaGetSymbolAddress((void**)&X16,  g_X16);
    cudaGetSymbolAddress((void**)&Wcat, g_Wcat16);
    cudaGetSymbolAddress((void**)&QKV,  g_QKV16);
    cudaGetSymbolAddress((void**)&VT16, g_VT16);
    cudaGetSymbolAddress((void**)&P16,  g_P16);
    cudaGetSymbolAddress((void**)&rsp,  g_rs);

    constexpr long long sQKV3 = (long long)SS * ND3;
    constexpr long long sV    = (long long)SS * DD;
    constexpr long long sP    = (long long)SS * SS;

    auto kProj  = mm_proj<3, DD, DD, ND3>;
    auto kScore = mm_w64<1, ND3, ND3, SS, sQKV3, sQKV3, sP>;
    auto kOut   = mm_w64<2, SS,  SS,  DD, sP,    sV,    sV>;

    cudaFuncSetAttribute(kProj,  cudaFuncAttributeMaxDynamicSharedMemorySize, SMEM_BYTES);
    cudaFuncSetAttribute(kScore, cudaFuncAttributeMaxDynamicSharedMemorySize, SMEM_BYTES);
    cudaFuncSetAttribute(kOut,   cudaFuncAttributeMaxDynamicSharedMemorySize, SMEM_BYTES);

    // 0) fused fp32 -> fp16 conversion (x + all weights, one launch)
    cvt_all_kernel<<<4096 + 3 * 512, 256>>>(x, Wq, Wk, Wv, X16, Wcat);

    // 1) Fused QKV projection; V columns written transposed to VT16
    dim3 gProj(ND3 / 96, (BB * SS) / 128, 1);
    kProj<<<gProj, 256, SMEM_BYTES>>>(X16, Wcat, QKV, VT16, DD);

    // 2) Scores + exp + mask + row-partial sums; triangular-packed grid
    const int TTILES = (SS / 128) * (SS / 128 + 1) / 2;   // 136
    dim3 gScore(TTILES, 1, BB);
    kScore<<<gScore, 128, SMEM_BYTES>>>(QKV, QKV + DD, P16, nullptr, rsp, DD);

    // 3) O = diag(1/rowsum) * (P~ @ V); heavy-first 1D grid
    dim3 gOut((DD / 128) * (SS / 128) * BB, 1, 1);
    kOut<<<gOut, 128, SMEM_BYTES>>>(P16, VT16, out, rsp, nullptr, SS);
}